// round 2
// baseline (speedup 1.0000x reference)
#include <cuda_runtime.h>
#include <cuda_bf16.h>

#define NPTS    512
#define NCH     64
#define CHG     32          // channels per block (channel half)
#define THREADS 1024
#define WARPS   (THREADS / 32)
#define SMEM_BYTES (3 * NPTS * CHG * 4)   // 196608 B

__global__ __launch_bounds__(THREADS, 1)
void triline_kernel(const float* __restrict__ coords,
                    const float* __restrict__ xl,
                    const float* __restrict__ yl,
                    const float* __restrict__ zl,
                    const float* __restrict__ grid,
                    float* __restrict__ out,
                    int B)
{
    extern __shared__ float smem[];
    float* sx = smem;
    float* sy = smem + NPTS * CHG;
    float* sz = smem + 2 * NPTS * CHG;

    const int cb = blockIdx.y * CHG;   // channel base: 0 or 32

    // Cooperative fill: each line slice is 512 rows x 32 ch, loaded as float4.
    // Global row stride is 64 floats; slice offset cb is 16B-aligned.
    for (int i = threadIdx.x; i < (NPTS * CHG) / 4; i += THREADS) {
        const int row = i >> 3;       // 8 float4 per 32-ch row
        const int q   = i & 7;
        const int goff = row * NCH + cb + 4 * q;
        reinterpret_cast<float4*>(sx)[i] = *reinterpret_cast<const float4*>(xl + goff);
        reinterpret_cast<float4*>(sy)[i] = *reinterpret_cast<const float4*>(yl + goff);
        reinterpret_cast<float4*>(sz)[i] = *reinterpret_cast<const float4*>(zl + goff);
    }

    const float g0     = grid[0];
    const float inv_dg = 1.0f / (grid[1] - grid[0]);
    __syncthreads();

    const int lane   = threadIdx.x & 31;
    const int wid    = threadIdx.x >> 5;
    const int stride = gridDim.x * WARPS;

    for (int p = blockIdx.x * WARPS + wid; p < B; p += stride) {
        // Broadcast loads (all lanes same address -> single transaction)
        const float c0 = __ldg(coords + 3 * p + 0);
        const float c1 = __ldg(coords + 3 * p + 1);
        const float c2 = __ldg(coords + 3 * p + 2);

        float acc;
        {
            float pos = (c0 - g0) * inv_dg;
            int   i0  = (int)floorf(pos);
            i0 = max(0, min(i0, NPTS - 2));
            float w  = pos - (float)i0;
            float f0 = sx[i0 * CHG + lane];
            float f1 = sx[i0 * CHG + CHG + lane];
            acc = f0 + w * (f1 - f0);
        }
        {
            float pos = (c1 - g0) * inv_dg;
            int   i0  = (int)floorf(pos);
            i0 = max(0, min(i0, NPTS - 2));
            float w  = pos - (float)i0;
            float f0 = sy[i0 * CHG + lane];
            float f1 = sy[i0 * CHG + CHG + lane];
            acc += f0 + w * (f1 - f0);
        }
        {
            float pos = (c2 - g0) * inv_dg;
            int   i0  = (int)floorf(pos);
            i0 = max(0, min(i0, NPTS - 2));
            float w  = pos - (float)i0;
            float f0 = sz[i0 * CHG + lane];
            float f1 = sz[i0 * CHG + CHG + lane];
            acc += f0 + w * (f1 - f0);
        }

        // Coalesced 128B store per warp
        out[(size_t)p * NCH + cb + lane] = acc;
    }
}

extern "C" void kernel_launch(void* const* d_in, const int* in_sizes, int n_in,
                              void* d_out, int out_size)
{
    const float* coords = (const float*)d_in[0];
    const float* xl     = (const float*)d_in[1];
    const float* yl     = (const float*)d_in[2];
    const float* zl     = (const float*)d_in[3];
    const float* grid   = (const float*)d_in[4];
    float*       out    = (float*)d_out;

    const int B = in_sizes[0] / 3;

    cudaFuncSetAttribute(triline_kernel,
                         cudaFuncAttributeMaxDynamicSharedMemorySize,
                         SMEM_BYTES);

    dim3 gridDim(74, 2);   // 148 CTAs = 1 wave on 148 SMs, one channel half per y
    triline_kernel<<<gridDim, THREADS, SMEM_BYTES>>>(coords, xl, yl, zl, grid, out, B);
}

// round 7
// speedup vs baseline: 2.1852x; 2.1852x over previous
#include <cuda_runtime.h>
#include <cuda_bf16.h>

#define NPTS    512
#define NCH     64
#define CHG     32          // channels per block (channel half)
#define THREADS 1024
#define WARPS   (THREADS / 32)
#define U       4           // points per warp per iteration
#define SMEM_BYTES (3 * NPTS * CHG * 4)   // 196608 B

__global__ __launch_bounds__(THREADS, 1)
void triline_kernel(const float* __restrict__ coords,
                    const float* __restrict__ xl,
                    const float* __restrict__ yl,
                    const float* __restrict__ zl,
                    const float* __restrict__ grid,
                    float* __restrict__ out,
                    int B)
{
    extern __shared__ float smem[];
    float* sx = smem;
    float* sy = smem + NPTS * CHG;
    float* sz = smem + 2 * NPTS * CHG;

    const int cb = blockIdx.y * CHG;   // channel base: 0 or 32

    // Cooperative fill: 512 rows x 32 ch per line, float4 loads.
    for (int i = threadIdx.x; i < (NPTS * CHG) / 4; i += THREADS) {
        const int row  = i >> 3;       // 8 float4 per 32-ch row
        const int q    = i & 7;
        const int goff = row * NCH + cb + 4 * q;
        reinterpret_cast<float4*>(sx)[i] = *reinterpret_cast<const float4*>(xl + goff);
        reinterpret_cast<float4*>(sy)[i] = *reinterpret_cast<const float4*>(yl + goff);
        reinterpret_cast<float4*>(sz)[i] = *reinterpret_cast<const float4*>(zl + goff);
    }

    const float g0     = grid[0];
    const float inv_dg = 1.0f / (grid[1] - grid[0]);
    __syncthreads();

    const int lane   = threadIdx.x & 31;
    const int wid    = threadIdx.x >> 5;
    const int stride = gridDim.x * WARPS * U;

    for (int p0 = (blockIdx.x * WARPS + wid) * U; p0 < B; p0 += stride) {
        // ---- one coalesced 48B load for 4 points' coords, then shuffle ----
        float v = 0.0f;
        const int cidx = 3 * p0 + lane;
        if (lane < 3 * U && cidx < 3 * B) v = __ldg(coords + cidx);

        int   i0[U][3];
        float w [U][3];
        #pragma unroll
        for (int j = 0; j < U; j++) {
            #pragma unroll
            for (int a = 0; a < 3; a++) {
                const float c   = __shfl_sync(0xffffffffu, v, 3 * j + a);
                const float pos = (c - g0) * inv_dg;
                int ii = (int)floorf(pos);
                ii = max(0, min(ii, NPTS - 2));
                i0[j][a] = ii * CHG + lane;
                w [j][a] = pos - (float)ii;
            }
        }

        // ---- issue all 24 gathers (independent -> high MLP) ----
        float f0[U][3], f1[U][3];
        #pragma unroll
        for (int j = 0; j < U; j++) {
            f0[j][0] = sx[i0[j][0]];        f1[j][0] = sx[i0[j][0] + CHG];
            f0[j][1] = sy[i0[j][1]];        f1[j][1] = sy[i0[j][1] + CHG];
            f0[j][2] = sz[i0[j][2]];        f1[j][2] = sz[i0[j][2] + CHG];
        }

        // ---- math + coalesced 128B stores ----
        #pragma unroll
        for (int j = 0; j < U; j++) {
            float acc = fmaf(w[j][0], f1[j][0] - f0[j][0], f0[j][0]);
            acc      += fmaf(w[j][1], f1[j][1] - f0[j][1], f0[j][1]);
            acc      += fmaf(w[j][2], f1[j][2] - f0[j][2], f0[j][2]);
            out[(size_t)(p0 + j) * NCH + cb + lane] = acc;
        }
    }
}

extern "C" void kernel_launch(void* const* d_in, const int* in_sizes, int n_in,
                              void* d_out, int out_size)
{
    const float* coords = (const float*)d_in[0];
    const float* xl     = (const float*)d_in[1];
    const float* yl     = (const float*)d_in[2];
    const float* zl     = (const float*)d_in[3];
    const float* grid   = (const float*)d_in[4];
    float*       out    = (float*)d_out;

    const int B = in_sizes[0] / 3;

    cudaFuncSetAttribute(triline_kernel,
                         cudaFuncAttributeMaxDynamicSharedMemorySize,
                         SMEM_BYTES);

    dim3 gridDim(74, 2);   // 148 CTAs = 1 wave, one channel half per y
    triline_kernel<<<gridDim, THREADS, SMEM_BYTES>>>(coords, xl, yl, zl, grid, out, B);
}

// round 10
// speedup vs baseline: 2.8862x; 1.3208x over previous
#include <cuda_runtime.h>
#include <cuda_bf16.h>

#define NPTS    512
#define NCH     64
#define CHG     32          // channels per block (channel half)
#define THREADS 1024
#define WARPS   (THREADS / 32)
#define U       4           // points per warp per iteration (one per 8-lane group)
#define SMEM_BYTES (3 * NPTS * CHG * 4)   // 196608 B

__global__ __launch_bounds__(THREADS, 1)
void triline_kernel(const float* __restrict__ coords,
                    const float* __restrict__ xl,
                    const float* __restrict__ yl,
                    const float* __restrict__ zl,
                    const float* __restrict__ grid,
                    float* __restrict__ out,
                    int B)
{
    extern __shared__ float smem[];

    const int cb = blockIdx.y * CHG;   // channel base: 0 or 32

    // Cooperative fill: 512 rows x 32 ch per line, float4 loads.
    {
        float* sx = smem;
        float* sy = smem +     NPTS * CHG;
        float* sz = smem + 2 * NPTS * CHG;
        for (int i = threadIdx.x; i < (NPTS * CHG) / 4; i += THREADS) {
            const int row  = i >> 3;       // 8 float4 per 32-ch row
            const int q    = i & 7;
            const int goff = row * NCH + cb + 4 * q;
            reinterpret_cast<float4*>(sx)[i] = *reinterpret_cast<const float4*>(xl + goff);
            reinterpret_cast<float4*>(sy)[i] = *reinterpret_cast<const float4*>(yl + goff);
            reinterpret_cast<float4*>(sz)[i] = *reinterpret_cast<const float4*>(zl + goff);
        }
    }

    const float g0     = grid[0];
    const float inv_dg = 1.0f / (grid[1] - grid[0]);
    __syncthreads();

    const int lane = threadIdx.x & 31;
    const int wid  = threadIdx.x >> 5;
    const int g    = lane >> 3;          // point group 0..3 within warp
    const int cl   = (lane & 7) << 2;    // channel offset (float4 granularity)

    const int stride = gridDim.x * WARPS * U;
    int p0 = (blockIdx.x * WARPS + wid) * U;

    // Prefetch coords for first iteration (lanes 0..11 hold 4 points x 3 axes)
    float v = 0.0f;
    if (lane < 3 * U) v = __ldg(coords + 3 * p0 + lane);

    while (p0 < B) {
        // Prefetch next iteration's coords (hide LDG latency behind this body)
        const int pn = p0 + stride;
        float vn = 0.0f;
        if (lane < 3 * U && pn < B) vn = __ldg(coords + 3 * pn + lane);

        float4 acc = make_float4(0.0f, 0.0f, 0.0f, 0.0f);

        #pragma unroll
        for (int a = 0; a < 3; a++) {
            // Each lane grabs its own point's coord for this axis
            const float c   = __shfl_sync(0xffffffffu, v, 3 * g + a);
            const float pos = (c - g0) * inv_dg;
            int ii = (int)floorf(pos);
            ii = max(0, min(ii, NPTS - 2));
            const float w = pos - (float)ii;

            const float* base = smem + a * (NPTS * CHG) + ii * CHG + cl;
            const float4 f0 = *reinterpret_cast<const float4*>(base);
            const float4 f1 = *reinterpret_cast<const float4*>(base + CHG);

            acc.x += fmaf(w, f1.x - f0.x, f0.x);
            acc.y += fmaf(w, f1.y - f0.y, f0.y);
            acc.z += fmaf(w, f1.z - f0.z, f0.z);
            acc.w += fmaf(w, f1.w - f0.w, f0.w);
        }

        // One 128B-per-quarter-warp coalesced store: 4 points x 32 channels
        *reinterpret_cast<float4*>(out + (size_t)(p0 + g) * NCH + cb + cl) = acc;

        p0 = pn;
        v  = vn;
    }
}

extern "C" void kernel_launch(void* const* d_in, const int* in_sizes, int n_in,
                              void* d_out, int out_size)
{
    const float* coords = (const float*)d_in[0];
    const float* xl     = (const float*)d_in[1];
    const float* yl     = (const float*)d_in[2];
    const float* zl     = (const float*)d_in[3];
    const float* grid   = (const float*)d_in[4];
    float*       out    = (float*)d_out;

    const int B = in_sizes[0] / 3;

    cudaFuncSetAttribute(triline_kernel,
                         cudaFuncAttributeMaxDynamicSharedMemorySize,
                         SMEM_BYTES);

    dim3 gridDim(74, 2);   // 148 CTAs = 1 wave, one channel half per y
    triline_kernel<<<gridDim, THREADS, SMEM_BYTES>>>(coords, xl, yl, zl, grid, out, B);
}

// round 11
// speedup vs baseline: 3.8820x; 1.3450x over previous
#include <cuda_runtime.h>
#include <cuda_fp16.h>

#define NPTS    512
#define NCH     64
#define THREADS 1024
#define WARPS   (THREADS / 32)
#define U       4                         // points per warp per iteration
#define LINE_HALFS (NPTS * NCH)           // 32768 halves per line
#define SMEM_BYTES (3 * LINE_HALFS * 2)   // 196608 B

__global__ __launch_bounds__(THREADS, 1)
void triline_kernel(const float* __restrict__ coords,
                    const float* __restrict__ xl,
                    const float* __restrict__ yl,
                    const float* __restrict__ zl,
                    const float* __restrict__ grid,
                    float* __restrict__ out,
                    int B)
{
    extern __shared__ __half2 smem2[];    // 3 lines x 16384 half2

    // ---- cooperative fill: fp32 global -> fp16 smem (contiguous, coalesced) ----
    {
        const float* srcs[3] = { xl, yl, zl };
        #pragma unroll
        for (int a = 0; a < 3; a++) {
            const float4* src = reinterpret_cast<const float4*>(srcs[a]);
            __half2*      dst = smem2 + a * (LINE_HALFS / 2);
            for (int i = threadIdx.x; i < LINE_HALFS / 4; i += THREADS) {
                const float4 f = src[i];
                dst[2 * i    ] = __floats2half2_rn(f.x, f.y);
                dst[2 * i + 1] = __floats2half2_rn(f.z, f.w);
            }
        }
    }

    const float g0     = grid[0];
    const float inv_dg = 1.0f / (grid[1] - grid[0]);
    __syncthreads();

    const int lane = threadIdx.x & 31;
    const int wid  = threadIdx.x >> 5;
    const int g    = lane >> 3;           // point group 0..3 within warp
    const int ch   = (lane & 7) << 3;     // channel offset in halves (8 ch per lane)

    const __half* sbase = reinterpret_cast<const __half*>(smem2);

    const int stride = gridDim.x * WARPS * U;
    int p0 = (blockIdx.x * WARPS + wid) * U;

    // Prefetch coords: lanes 0..11 hold 4 points x 3 axes
    float v = 0.0f;
    if (lane < 3 * U && p0 < B) v = __ldg(coords + 3 * p0 + lane);

    while (p0 < B) {
        const int pn = p0 + stride;
        float vn = 0.0f;
        if (lane < 3 * U && pn < B) vn = __ldg(coords + 3 * pn + lane);

        __half2 a0, a1, a2, a3;   // accumulators: 8 channels as 4 half2

        #pragma unroll
        for (int a = 0; a < 3; a++) {
            const float c   = __shfl_sync(0xffffffffu, v, 3 * g + a);
            const float pos = (c - g0) * inv_dg;
            int ii = (int)floorf(pos);
            ii = max(0, min(ii, NPTS - 2));
            const __half2 w2 = __float2half2_rn(pos - (float)ii);

            const __half* base = sbase + a * LINE_HALFS + ii * NCH + ch;
            const uint4 u0 = *reinterpret_cast<const uint4*>(base);        // row ii
            const uint4 u1 = *reinterpret_cast<const uint4*>(base + NCH);  // row ii+1

            const __half2 f00 = *reinterpret_cast<const __half2*>(&u0.x);
            const __half2 f01 = *reinterpret_cast<const __half2*>(&u0.y);
            const __half2 f02 = *reinterpret_cast<const __half2*>(&u0.z);
            const __half2 f03 = *reinterpret_cast<const __half2*>(&u0.w);
            const __half2 f10 = *reinterpret_cast<const __half2*>(&u1.x);
            const __half2 f11 = *reinterpret_cast<const __half2*>(&u1.y);
            const __half2 f12 = *reinterpret_cast<const __half2*>(&u1.z);
            const __half2 f13 = *reinterpret_cast<const __half2*>(&u1.w);

            const __half2 r0 = __hfma2(w2, __hsub2(f10, f00), f00);
            const __half2 r1 = __hfma2(w2, __hsub2(f11, f01), f01);
            const __half2 r2 = __hfma2(w2, __hsub2(f12, f02), f02);
            const __half2 r3 = __hfma2(w2, __hsub2(f13, f03), f03);

            if (a == 0) { a0 = r0; a1 = r1; a2 = r2; a3 = r3; }
            else {
                a0 = __hadd2(a0, r0);
                a1 = __hadd2(a1, r1);
                a2 = __hadd2(a2, r2);
                a3 = __hadd2(a3, r3);
            }
        }

        // Convert to fp32 and store 8 channels: two float4 = 32B per lane,
        // 8 lanes per point -> 256B contiguous per point.
        const float2 o0 = __half22float2(a0);
        const float2 o1 = __half22float2(a1);
        const float2 o2 = __half22float2(a2);
        const float2 o3 = __half22float2(a3);

        float* optr = out + (size_t)(p0 + g) * NCH + ch;
        *reinterpret_cast<float4*>(optr)     = make_float4(o0.x, o0.y, o1.x, o1.y);
        *reinterpret_cast<float4*>(optr + 4) = make_float4(o2.x, o2.y, o3.x, o3.y);

        p0 = pn;
        v  = vn;
    }
}

extern "C" void kernel_launch(void* const* d_in, const int* in_sizes, int n_in,
                              void* d_out, int out_size)
{
    const float* coords = (const float*)d_in[0];
    const float* xl     = (const float*)d_in[1];
    const float* yl     = (const float*)d_in[2];
    const float* zl     = (const float*)d_in[3];
    const float* grid   = (const float*)d_in[4];
    float*       out    = (float*)d_out;

    const int B = in_sizes[0] / 3;

    cudaFuncSetAttribute(triline_kernel,
                         cudaFuncAttributeMaxDynamicSharedMemorySize,
                         SMEM_BYTES);

    triline_kernel<<<148, THREADS, SMEM_BYTES>>>(coords, xl, yl, zl, grid, out, B);
}